// round 1
// baseline (speedup 1.0000x reference)
#include <cuda_runtime.h>

// LSTMNet: 3-layer LSTM (H=6, input=1), B=8192, T=512, FC head on final h2.
// One thread per batch element; all state in registers; weights preprocessed
// (transposed column-major, bias-fused, exp2-prescaled) into __device__ scratch.

#define HD 6
#define GD 24
#define TT 512

// pack layout (floats):
//   0   : b0[24]            (prescaled)
//   24  : Wih0 col [24]     (prescaled; input dim = 1)
//   48  : Whh0 [6 cols][24] (col-major, prescaled)
//   192 : b1[24]
//   216 : Wih1 [6][24]
//   360 : Whh1 [6][24]
//   504 : b2[24]
//   528 : Wih2 [6][24]
//   672 : Whh2 [6][24]
//   816 : fc_w[6], 822: fc_b
#define PACK_N 832
__device__ float g_pack[PACK_N];

// row scale: sigmoid rows (i,f,o) -> -log2(e); tanh rows (g) -> -2*log2(e)
__device__ __forceinline__ float row_scale(int g) {
    return (g / 6 == 2) ? -2.88539008177793f : -1.44269504088896f;
}

__global__ void prep_kernel(
    const float* __restrict__ Wih0, const float* __restrict__ Whh0,
    const float* __restrict__ bih0, const float* __restrict__ bhh0,
    const float* __restrict__ Wih1, const float* __restrict__ Whh1,
    const float* __restrict__ bih1, const float* __restrict__ bhh1,
    const float* __restrict__ Wih2, const float* __restrict__ Whh2,
    const float* __restrict__ bih2, const float* __restrict__ bhh2,
    const float* __restrict__ fcw, const float* __restrict__ fcb)
{
    int tid = threadIdx.x;
    for (int idx = tid; idx < 24; idx += blockDim.x) {
        float s = row_scale(idx);
        g_pack[0   + idx] = (bih0[idx] + bhh0[idx]) * s;
        g_pack[192 + idx] = (bih1[idx] + bhh1[idx]) * s;
        g_pack[504 + idx] = (bih2[idx] + bhh2[idx]) * s;
        g_pack[24  + idx] = Wih0[idx] * s;
    }
    for (int idx = tid; idx < 144; idx += blockDim.x) {
        int g = idx % 24, j = idx / 24;   // col-major: pack[j*24 + g] = W[g][j]
        float s = row_scale(g);
        g_pack[48  + idx] = Whh0[g * HD + j] * s;
        g_pack[216 + idx] = Wih1[g * HD + j] * s;
        g_pack[360 + idx] = Whh1[g * HD + j] * s;
        g_pack[528 + idx] = Wih2[g * HD + j] * s;
        g_pack[672 + idx] = Whh2[g * HD + j] * s;
    }
    if (tid < 6) g_pack[816 + tid] = fcw[tid];
    if (tid == 0) g_pack[822] = fcb[0];
}

// ---- fast math primitives (accurate enough: ~1e-7 vs 1e-3 gate) ----
__device__ __forceinline__ float ex2_ap(float x) {
    float y; asm("ex2.approx.f32 %0, %1;" : "=f"(y) : "f"(x)); return y;
}
__device__ __forceinline__ float rcp_ap(float x) {
    float y; asm("rcp.approx.f32 %0, %1;" : "=f"(y) : "f"(x)); return y;
}
// a = -z*log2e  -> sigmoid(z)
__device__ __forceinline__ float sig_pre(float a) {
    return rcp_ap(1.0f + ex2_ap(a));
}
// a = -2z*log2e -> tanh(z)
__device__ __forceinline__ float tanh_pre(float a) {
    return fmaf(rcp_ap(1.0f + ex2_ap(a)), 2.0f, -1.0f);
}
__device__ __forceinline__ float tanh_full(float z) {
    return tanh_pre(z * -2.88539008177793f);
}

__device__ __forceinline__ void load_bias(float acc[GD], const float* bp) {
    const float4* b4 = reinterpret_cast<const float4*>(bp);
#pragma unroll
    for (int q = 0; q < 6; q++) {
        float4 w = b4[q];
        acc[4*q+0] = w.x; acc[4*q+1] = w.y; acc[4*q+2] = w.z; acc[4*q+3] = w.w;
    }
}

__device__ __forceinline__ void accum_col(float acc[GD], const float* colp, float v) {
    const float4* c4 = reinterpret_cast<const float4*>(colp);
#pragma unroll
    for (int q = 0; q < 6; q++) {
        float4 w = c4[q];
        acc[4*q+0] = fmaf(w.x, v, acc[4*q+0]);
        acc[4*q+1] = fmaf(w.y, v, acc[4*q+1]);
        acc[4*q+2] = fmaf(w.z, v, acc[4*q+2]);
        acc[4*q+3] = fmaf(w.w, v, acc[4*q+3]);
    }
}

__device__ __forceinline__ void cell_update(const float acc[GD], float h[HD], float c[HD]) {
#pragma unroll
    for (int k = 0; k < HD; k++) {
        float iv = sig_pre(acc[k]);
        float fv = sig_pre(acc[6 + k]);
        float gv = tanh_pre(acc[12 + k]);
        float ov = sig_pre(acc[18 + k]);
        float cn = fmaf(fv, c[k], iv * gv);
        c[k] = cn;
        h[k] = ov * tanh_full(cn);
    }
}

__global__ void __launch_bounds__(32, 8)
lstm_kernel(const float* __restrict__ x, float* __restrict__ out)
{
    __shared__ float sw[PACK_N];
    int tid = threadIdx.x;
#pragma unroll
    for (int i = tid; i < PACK_N; i += 32) sw[i] = g_pack[i];
    __syncthreads();

    int b = blockIdx.x * 32 + tid;
    const float* xp = x + (size_t)b * TT;

    float h0[HD], c0[HD], h1[HD], c1[HD], h2[HD], c2[HD];
#pragma unroll
    for (int k = 0; k < HD; k++) {
        h0[k] = c0[k] = h1[k] = c1[k] = h2[k] = c2[k] = 0.0f;
    }

#pragma unroll 1
    for (int t = 0; t < TT; t++) {
        float xt = __ldg(xp + t);
        float acc[GD];

        // ---- layer 0 (input dim 1) ----
        load_bias(acc, &sw[0]);
        accum_col(acc, &sw[24], xt);
#pragma unroll
        for (int j = 0; j < HD; j++) accum_col(acc, &sw[48 + j * GD], h0[j]);
        cell_update(acc, h0, c0);

        // ---- layer 1 ----
        load_bias(acc, &sw[192]);
#pragma unroll
        for (int j = 0; j < HD; j++) accum_col(acc, &sw[216 + j * GD], h0[j]);
#pragma unroll
        for (int j = 0; j < HD; j++) accum_col(acc, &sw[360 + j * GD], h1[j]);
        cell_update(acc, h1, c1);

        // ---- layer 2 ----
        load_bias(acc, &sw[504]);
#pragma unroll
        for (int j = 0; j < HD; j++) accum_col(acc, &sw[528 + j * GD], h1[j]);
#pragma unroll
        for (int j = 0; j < HD; j++) accum_col(acc, &sw[672 + j * GD], h2[j]);
        cell_update(acc, h2, c2);
    }

    // FC head: out[b] = dot(h2, fc_w) + fc_b
    float r = sw[822];
#pragma unroll
    for (int k = 0; k < HD; k++) r = fmaf(h2[k], sw[816 + k], r);
    out[b] = r;
}

extern "C" void kernel_launch(void* const* d_in, const int* in_sizes, int n_in,
                              void* d_out, int out_size)
{
    const float* x = (const float*)d_in[0];
    int B = in_sizes[0] / TT;          // 8192
    int grid = (B + 31) / 32;          // 256

    prep_kernel<<<1, 256>>>(
        (const float*)d_in[1],  (const float*)d_in[2],
        (const float*)d_in[3],  (const float*)d_in[4],
        (const float*)d_in[5],  (const float*)d_in[6],
        (const float*)d_in[7],  (const float*)d_in[8],
        (const float*)d_in[9],  (const float*)d_in[10],
        (const float*)d_in[11], (const float*)d_in[12],
        (const float*)d_in[13], (const float*)d_in[14]);

    lstm_kernel<<<grid, 32>>>(x, (float*)d_out);
}

// round 2
// speedup vs baseline: 1.4626x; 1.4626x over previous
#include <cuda_runtime.h>

// LSTMNet: 3-layer LSTM (H=6, input=1), B=8192, T=512, FC head on final h2.
// Round 2: 6-lane hidden-dim split. Lane owns hidden unit k of one element:
// computes 4 gate pre-activations + local cell update. 5 elements per warp
// (30 active lanes) -> 1639 warps, ~2.8/SMSP. h broadcast via SHFL.

#define HD 6
#define GD 24
#define TT 512
#define PK 144                 // floats per lane-k weight slice
__device__ float g_packk[6 * PK];

// per-k slice layout (all prescaled: sigmoid rows * -log2e, tanh rows * -2log2e):
//   0: b0[4] (i,f,g,o)   4: wx0[4]   8+j*4: Whh0 col j [4]   (j=0..5)
//  32: b1[4]            36+j*4: Wih1 col j   60+j*4: Whh1 col j
//  84: b2[4]            88+j*4: Wih2 col j  112+j*4: Whh2 col j
// 136: fc_w[k]  137: fc_b

__global__ void prep_kernel(
    const float* __restrict__ Wih0, const float* __restrict__ Whh0,
    const float* __restrict__ bih0, const float* __restrict__ bhh0,
    const float* __restrict__ Wih1, const float* __restrict__ Whh1,
    const float* __restrict__ bih1, const float* __restrict__ bhh1,
    const float* __restrict__ Wih2, const float* __restrict__ Whh2,
    const float* __restrict__ bih2, const float* __restrict__ bhh2,
    const float* __restrict__ fcw, const float* __restrict__ fcb)
{
    int tid = threadIdx.x;
    if (tid < 24) {
        int k = tid / 4, g = tid % 4;
        float s = (g == 2) ? -2.88539008177793f : -1.44269504088896f;
        int row = g * HD + k;             // PyTorch gate order i,f,g,o
        float* p = g_packk + k * PK;
        p[0 + g]  = (bih0[row] + bhh0[row]) * s;
        p[4 + g]  = Wih0[row] * s;        // input dim = 1
        p[32 + g] = (bih1[row] + bhh1[row]) * s;
        p[84 + g] = (bih2[row] + bhh2[row]) * s;
        for (int j = 0; j < HD; j++) {
            p[8   + j * 4 + g] = Whh0[row * HD + j] * s;
            p[36  + j * 4 + g] = Wih1[row * HD + j] * s;
            p[60  + j * 4 + g] = Whh1[row * HD + j] * s;
            p[88  + j * 4 + g] = Wih2[row * HD + j] * s;
            p[112 + j * 4 + g] = Whh2[row * HD + j] * s;
        }
    }
    if (tid < 6) {
        g_packk[tid * PK + 136] = fcw[tid];
        g_packk[tid * PK + 137] = fcb[0];
    }
}

// ---- fast math primitives (~1e-7 accuracy, proven in R1) ----
__device__ __forceinline__ float ex2_ap(float x) {
    float y; asm("ex2.approx.f32 %0, %1;" : "=f"(y) : "f"(x)); return y;
}
__device__ __forceinline__ float rcp_ap(float x) {
    float y; asm("rcp.approx.f32 %0, %1;" : "=f"(y) : "f"(x)); return y;
}
__device__ __forceinline__ float sig_pre(float a)  {          // a = -z*log2e
    return rcp_ap(1.0f + ex2_ap(a));
}
__device__ __forceinline__ float tanh_pre(float a) {          // a = -2z*log2e
    return fmaf(rcp_ap(1.0f + ex2_ap(a)), 2.0f, -1.0f);
}
__device__ __forceinline__ float tanh_full(float z) {
    return tanh_pre(z * -2.88539008177793f);
}

__device__ __forceinline__ void cell_up(float ai, float af, float ag, float ao,
                                        float& h, float& c)
{
    float iv = sig_pre(ai);
    float fv = sig_pre(af);
    float gv = tanh_pre(ag);
    float ov = sig_pre(ao);
    c = fmaf(fv, c, iv * gv);
    h = ov * tanh_full(c);
}

__global__ void __launch_bounds__(128)
lstm6_kernel(const float* __restrict__ x, float* __restrict__ out, int B)
{
    __shared__ float sw[6 * PK];
    for (int i = threadIdx.x; i < 6 * PK; i += 128) sw[i] = g_packk[i];
    __syncthreads();

    int wid  = blockIdx.x * 4 + (threadIdx.x >> 5);
    int lane = threadIdx.x & 31;
    if (wid * 5 >= B) return;                       // warp-uniform exit

    int sub = lane / HD;                            // 0..4 active, 5 = spare
    int k   = lane - sub * HD;
    int subbase = sub * HD;
    int elem = wid * 5 + (sub < 5 ? sub : 0);
    bool store_ok = (sub < 5) && (elem < B) && (k == 0);
    if (elem >= B) elem = B - 1;                    // clamp loads only

    const float* pk = sw + k * PK;
    const float4* wk4 = reinterpret_cast<const float4*>(pk);

    // hoist layer-0 weights + biases + fc to registers
    float b0i = pk[0], b0f = pk[1], b0g = pk[2], b0o = pk[3];
    float wxi = pk[4], wxf = pk[5], wxg = pk[6], wxo = pk[7];
    float w0[24];
#pragma unroll
    for (int i = 0; i < 24; i++) w0[i] = pk[8 + i];
    float b1i = pk[32], b1f = pk[33], b1g = pk[34], b1o = pk[35];
    float b2i = pk[84], b2f = pk[85], b2g = pk[86], b2o = pk[87];
    float fcwk = pk[136], fcbv = pk[137];

    const float4* xp = reinterpret_cast<const float4*>(x + (size_t)elem * TT);

    float h0 = 0.f, c0 = 0.f, h1 = 0.f, c1 = 0.f, h2 = 0.f, c2 = 0.f;

#pragma unroll 1
    for (int t4 = 0; t4 < TT / 4; t4++) {
        float4 xq = __ldg(xp + t4);
#pragma unroll
        for (int u = 0; u < 4; u++) {
            float xt = (u == 0) ? xq.x : (u == 1) ? xq.y : (u == 2) ? xq.z : xq.w;

            // ---- layer 0 ----
            float ai = fmaf(wxi, xt, b0i);
            float af = fmaf(wxf, xt, b0f);
            float ag = fmaf(wxg, xt, b0g);
            float ao = fmaf(wxo, xt, b0o);
#pragma unroll
            for (int j = 0; j < HD; j++) {
                float v = __shfl_sync(0xffffffffu, h0, subbase + j);
                ai = fmaf(w0[j * 4 + 0], v, ai);
                af = fmaf(w0[j * 4 + 1], v, af);
                ag = fmaf(w0[j * 4 + 2], v, ag);
                ao = fmaf(w0[j * 4 + 3], v, ao);
            }
            cell_up(ai, af, ag, ao, h0, c0);

            // ---- layer 1 ----
            ai = b1i; af = b1f; ag = b1g; ao = b1o;
#pragma unroll
            for (int j = 0; j < HD; j++) {
                float v = __shfl_sync(0xffffffffu, h0, subbase + j);
                float4 w = wk4[9 + j];
                ai = fmaf(w.x, v, ai); af = fmaf(w.y, v, af);
                ag = fmaf(w.z, v, ag); ao = fmaf(w.w, v, ao);
            }
#pragma unroll
            for (int j = 0; j < HD; j++) {
                float v = __shfl_sync(0xffffffffu, h1, subbase + j);
                float4 w = wk4[15 + j];
                ai = fmaf(w.x, v, ai); af = fmaf(w.y, v, af);
                ag = fmaf(w.z, v, ag); ao = fmaf(w.w, v, ao);
            }
            cell_up(ai, af, ag, ao, h1, c1);

            // ---- layer 2 ----
            ai = b2i; af = b2f; ag = b2g; ao = b2o;
#pragma unroll
            for (int j = 0; j < HD; j++) {
                float v = __shfl_sync(0xffffffffu, h1, subbase + j);
                float4 w = wk4[22 + j];
                ai = fmaf(w.x, v, ai); af = fmaf(w.y, v, af);
                ag = fmaf(w.z, v, ag); ao = fmaf(w.w, v, ao);
            }
#pragma unroll
            for (int j = 0; j < HD; j++) {
                float v = __shfl_sync(0xffffffffu, h2, subbase + j);
                float4 w = wk4[28 + j];
                ai = fmaf(w.x, v, ai); af = fmaf(w.y, v, af);
                ag = fmaf(w.z, v, ag); ao = fmaf(w.w, v, ao);
            }
            cell_up(ai, af, ag, ao, h2, c2);
        }
    }

    // FC head: out[e] = sum_k h2[k]*fc_w[k] + fc_b  (reduce across 6 lanes)
    float r = h2 * fcwk;
    float s = fcbv;
#pragma unroll
    for (int j = 0; j < HD; j++)
        s += __shfl_sync(0xffffffffu, r, subbase + j);
    if (store_ok) out[elem] = s;
}

extern "C" void kernel_launch(void* const* d_in, const int* in_sizes, int n_in,
                              void* d_out, int out_size)
{
    const float* x = (const float*)d_in[0];
    int B = in_sizes[0] / TT;                  // 8192
    int warps  = (B + 4) / 5;                  // 1639
    int blocks = (warps + 3) / 4;              // 410

    prep_kernel<<<1, 64>>>(
        (const float*)d_in[1],  (const float*)d_in[2],
        (const float*)d_in[3],  (const float*)d_in[4],
        (const float*)d_in[5],  (const float*)d_in[6],
        (const float*)d_in[7],  (const float*)d_in[8],
        (const float*)d_in[9],  (const float*)d_in[10],
        (const float*)d_in[11], (const float*)d_in[12],
        (const float*)d_in[13], (const float*)d_in[14]);

    lstm6_kernel<<<blocks, 128>>>(x, (float*)d_out, B);
}

// round 3
// speedup vs baseline: 1.9783x; 1.3526x over previous
#include <cuda_runtime.h>

// LSTMNet: 3-layer LSTM (H=6, input=1), B=8192, T=512, FC head on final h2.
// Round 3: 6-lane hidden split (5 elem/warp) +
//   - conflict-free smem stride (PK=164 floats, 656B == 16 mod 128)
//   - fma.rn.f32x2 packed matvec: (i,f) and (g,o) gate pairs
//   - SHFL-once-reuse h broadcast vectors (18 SHFL/step instead of 30)
//   - paired reciprocals: one rcp per sigmoid pair

#define HD 6
#define TT 512
#define PK 164                 // floats per lane-k slice; 656B stride -> no bank conflicts
__device__ float g_packk[6 * PK];

// per-k slice layout (floats, prescaled: sigmoid rows * -log2e, tanh row * -2log2e):
//   0: b0[4] (i,f,g,o)   4: wx0[4]   8+4j: Whh0 col j
//  32: b1[4]   36+4j: Wih1 col j   60+4j: Whh1 col j
//  84: b2[4]   88+4j: Wih2 col j  112+4j: Whh2 col j
// 136: fc_w[k]  137: fc_b

__global__ void prep_kernel(
    const float* __restrict__ Wih0, const float* __restrict__ Whh0,
    const float* __restrict__ bih0, const float* __restrict__ bhh0,
    const float* __restrict__ Wih1, const float* __restrict__ Whh1,
    const float* __restrict__ bih1, const float* __restrict__ bhh1,
    const float* __restrict__ Wih2, const float* __restrict__ Whh2,
    const float* __restrict__ bih2, const float* __restrict__ bhh2,
    const float* __restrict__ fcw, const float* __restrict__ fcb)
{
    int tid = threadIdx.x;
    if (tid < 24) {
        int k = tid / 4, g = tid % 4;
        float s = (g == 2) ? -2.88539008177793f : -1.44269504088896f;
        int row = g * HD + k;             // PyTorch gate order i,f,g,o
        float* p = g_packk + k * PK;
        p[0 + g]  = (bih0[row] + bhh0[row]) * s;
        p[4 + g]  = Wih0[row] * s;        // input dim = 1
        p[32 + g] = (bih1[row] + bhh1[row]) * s;
        p[84 + g] = (bih2[row] + bhh2[row]) * s;
        for (int j = 0; j < HD; j++) {
            p[8   + j * 4 + g] = Whh0[row * HD + j] * s;
            p[36  + j * 4 + g] = Wih1[row * HD + j] * s;
            p[60  + j * 4 + g] = Whh1[row * HD + j] * s;
            p[88  + j * 4 + g] = Wih2[row * HD + j] * s;
            p[112 + j * 4 + g] = Whh2[row * HD + j] * s;
        }
    }
    if (tid < 6) {
        g_packk[tid * PK + 136] = fcw[tid];
        g_packk[tid * PK + 137] = fcb[0];
    }
}

typedef unsigned long long ull;

// ---- f32x2 + fast-math primitives ----
__device__ __forceinline__ void fma2(ull& d, ull a, ull b, ull c) {
    asm("fma.rn.f32x2 %0, %1, %2, %3;" : "=l"(d) : "l"(a), "l"(b), "l"(c));
}
__device__ __forceinline__ ull pack2(float x, float y) {
    ull d; asm("mov.b64 %0, {%1, %2};" : "=l"(d) : "f"(x), "f"(y)); return d;
}
__device__ __forceinline__ void unpack2(float& x, float& y, ull v) {
    asm("mov.b64 {%0, %1}, %2;" : "=f"(x), "=f"(y) : "l"(v));
}
__device__ __forceinline__ float ex2_ap(float x) {
    float y; asm("ex2.approx.f32 %0, %1;" : "=f"(y) : "f"(x)); return y;
}
__device__ __forceinline__ float rcp_ap(float x) {
    float y; asm("rcp.approx.f32 %0, %1;" : "=f"(y) : "f"(x)); return y;
}

// aif = (-zi*log2e, -zf*log2e), ago = (-2zg*log2e, -zo*log2e)
// paired reciprocals: one rcp per gate pair; limits are exact on saturation.
__device__ __forceinline__ void cell(ull aif, ull ago, float& c, float& h) {
    float ai, af, ag, ao;
    unpack2(ai, af, aif);
    unpack2(ag, ao, ago);
    float ei = ex2_ap(ai), ef = ex2_ap(af), eg = ex2_ap(ag), eo = ex2_ap(ao);
    float a1 = 1.f + ei, a2 = 1.f + ef, a3 = 1.f + eg, a4 = 1.f + eo;
    float r1 = rcp_ap(a1 * a2);
    float r2 = rcp_ap(a3 * a4);
    float si = r1 * a2;                       // sigmoid(zi)
    float sf = r1 * a1;                       // sigmoid(zf)
    float so = r2 * a3;                       // sigmoid(zo)
    float tg = fmaf(r2 * a4, 2.f, -1.f);      // tanh(zg)
    c = fmaf(sf, c, si * tg);
    float ec = ex2_ap(c * -2.88539008177793f);
    float th = fmaf(rcp_ap(1.f + ec), 2.f, -1.f);
    h = so * th;
}

__global__ void __launch_bounds__(128)
lstm6_kernel(const float* __restrict__ x, float* __restrict__ out, int B)
{
    __shared__ __align__(16) float sw[6 * PK];
    for (int i = threadIdx.x; i < 6 * PK; i += 128) sw[i] = g_packk[i];
    __syncthreads();

    int wid  = blockIdx.x * 4 + (threadIdx.x >> 5);
    int lane = threadIdx.x & 31;
    if (wid * 5 >= B) return;                       // warp-uniform exit

    int sub = lane / HD;                            // 0..4 active, 5 = spare
    int k   = lane - sub * HD;
    int sb  = (sub < 5) ? sub * HD : 0;             // shuffle base
    int elem = wid * 5 + (sub < 5 ? sub : 0);
    bool store_ok = (sub < 5) && (elem < B) && (k == 0);
    if (elem >= B) elem = B - 1;                    // clamp loads only

    const float* pk = sw + k * PK;
    const ull* pk8 = reinterpret_cast<const ull*>(pk);

    // hoisted constants: layer0 weights/biases, layer1/2 biases, fc
    ull b0if = pk8[0],  b0go = pk8[1];
    ull wxif = pk8[2],  wxgo = pk8[3];
    ull w0r[12];                                    // Whh0: (if,go) per col
#pragma unroll
    for (int j = 0; j < 12; j++) w0r[j] = pk8[4 + j];
    ull b1if = pk8[16], b1go = pk8[17];
    ull b2if = pk8[42], b2go = pk8[43];
    float fcwk = pk[136], fcbv = pk[137];

    const ull* w1i = pk8 + 18;                      // Wih1 cols (if,go)
    const ull* w1h = pk8 + 30;                      // Whh1
    const ull* w2i = pk8 + 44;                      // Wih2
    const ull* w2h = pk8 + 56;                      // Whh2

    const float4* xp = reinterpret_cast<const float4*>(x + (size_t)elem * TT);

    float h0v[HD], h1v[HD], h2v[HD];
    float c0 = 0.f, c1 = 0.f, c2 = 0.f;
#pragma unroll
    for (int j = 0; j < HD; j++) h0v[j] = h1v[j] = h2v[j] = 0.f;
    float h2own = 0.f;

#pragma unroll 1
    for (int t4 = 0; t4 < TT / 4; t4++) {
        float4 xq = __ldg(xp + t4);
#pragma unroll
        for (int u = 0; u < 4; u++) {
            float xt = (u == 0) ? xq.x : (u == 1) ? xq.y : (u == 2) ? xq.z : xq.w;

            // ---- layer 0: gates = b0 + wx*x + Whh0 @ h0v ----
            ull xx = pack2(xt, xt);
            ull aif, ago;
            fma2(aif, wxif, xx, b0if);
            fma2(ago, wxgo, xx, b0go);
#pragma unroll
            for (int j = 0; j < HD; j++) {
                ull vv = pack2(h0v[j], h0v[j]);
                fma2(aif, w0r[2 * j],     vv, aif);
                fma2(ago, w0r[2 * j + 1], vv, ago);
            }
            float h0n;
            cell(aif, ago, c0, h0n);
#pragma unroll
            for (int j = 0; j < HD; j++)
                h0v[j] = __shfl_sync(0xffffffffu, h0n, sb + j);

            // ---- layer 1: b1 + Wih1 @ h0v(new) + Whh1 @ h1v(old) ----
            aif = b1if; ago = b1go;
#pragma unroll
            for (int j = 0; j < HD; j++) {
                ull vv = pack2(h0v[j], h0v[j]);
                fma2(aif, w1i[2 * j],     vv, aif);
                fma2(ago, w1i[2 * j + 1], vv, ago);
            }
#pragma unroll
            for (int j = 0; j < HD; j++) {
                ull vv = pack2(h1v[j], h1v[j]);
                fma2(aif, w1h[2 * j],     vv, aif);
                fma2(ago, w1h[2 * j + 1], vv, ago);
            }
            float h1n;
            cell(aif, ago, c1, h1n);
#pragma unroll
            for (int j = 0; j < HD; j++)
                h1v[j] = __shfl_sync(0xffffffffu, h1n, sb + j);

            // ---- layer 2: b2 + Wih2 @ h1v(new) + Whh2 @ h2v(old) ----
            aif = b2if; ago = b2go;
#pragma unroll
            for (int j = 0; j < HD; j++) {
                ull vv = pack2(h1v[j], h1v[j]);
                fma2(aif, w2i[2 * j],     vv, aif);
                fma2(ago, w2i[2 * j + 1], vv, ago);
            }
#pragma unroll
            for (int j = 0; j < HD; j++) {
                ull vv = pack2(h2v[j], h2v[j]);
                fma2(aif, w2h[2 * j],     vv, aif);
                fma2(ago, w2h[2 * j + 1], vv, ago);
            }
            cell(aif, ago, c2, h2own);
#pragma unroll
            for (int j = 0; j < HD; j++)
                h2v[j] = __shfl_sync(0xffffffffu, h2own, sb + j);
        }
    }

    // FC head: out[e] = sum_k h2[k]*fc_w[k] + fc_b  (reduce across the 6 lanes)
    float r = h2own * fcwk;
    float s = fcbv;
#pragma unroll
    for (int j = 0; j < HD; j++)
        s += __shfl_sync(0xffffffffu, r, sb + j);
    if (store_ok) out[elem] = s;
}

extern "C" void kernel_launch(void* const* d_in, const int* in_sizes, int n_in,
                              void* d_out, int out_size)
{
    const float* x = (const float*)d_in[0];
    int B = in_sizes[0] / TT;                  // 8192
    int warps  = (B + 4) / 5;                  // 1639
    int blocks = (warps + 3) / 4;              // 410

    prep_kernel<<<1, 64>>>(
        (const float*)d_in[1],  (const float*)d_in[2],
        (const float*)d_in[3],  (const float*)d_in[4],
        (const float*)d_in[5],  (const float*)d_in[6],
        (const float*)d_in[7],  (const float*)d_in[8],
        (const float*)d_in[9],  (const float*)d_in[10],
        (const float*)d_in[11], (const float*)d_in[12],
        (const float*)d_in[13], (const float*)d_in[14]);

    lstm6_kernel<<<blocks, 128>>>(x, (float*)d_out, B);
}